// round 15
// baseline (speedup 1.0000x reference)
#include <cuda_runtime.h>
#include <cuda_fp16.h>
#include <cstdint>

#define TB_ 131072
#define B_  32

// ---------------- device scratch (no allocation allowed) ----------------
__device__ float g_hbre[B_ * 512];             // [b][nt*128 + hl*4 + q]
__device__ uint4 g_wfrag4[4 * 8 * 8 * 32];     // [nt][ks][jj][lane] -> {bA0,bA1,bB0,bB1}
// A frags for 64-row tiles: [mt64(2048)][ks(8)][rg(4)][lane(32)] -> uint4
__device__ uint4 g_afrag[2048 * 8 * 4 * 32];   // 33.5 MB

// ---------------- helpers ----------------
__device__ __forceinline__ float tanh_ap(float x) {
    float y; asm("tanh.approx.f32 %0, %1;" : "=f"(y) : "f"(x)); return y;
}

// ---------------- fused prep kernel ----------------
// blocks [0,64):     Hb = h0 @ W_hh^T + b_ih + b_hh (gate-interleaved layout)
// blocks [64,96):    W_ih -> fp16 B-frag uint4 pairs, in-lane gate/head mapping
// blocks [96,2144):  input fp32 -> fp16 A frags via coalesced smem transpose
__global__ void prep_all(const float* __restrict__ input, const float* __restrict__ h0,
                         const float* __restrict__ W_hh, const float* __restrict__ b_ih,
                         const float* __restrict__ b_hh, const float* __restrict__ W_ih) {
    __shared__ __align__(16) unsigned short As[64 * 136];   // padded fp16 tile (17.4 KB)
    const int bx = blockIdx.x, tid = threadIdx.x;
    if (bx < 64) {
        int idx = bx * 256 + tid;
        int b = idx & 31, g = idx >> 5;
        const float4* wv = (const float4*)(W_hh + g * 128);
        const float4* hv = (const float4*)(h0 + b * 128);
        float s0 = b_ih[g] + b_hh[g], s1 = 0.f, s2 = 0.f, s3 = 0.f;
#pragma unroll
        for (int k = 0; k < 32; k++) {
            float4 w = wv[k], h = hv[k];
            s0 += w.x * h.x; s1 += w.y * h.y; s2 += w.z * h.z; s3 += w.w * h.w;
        }
        float s = (s0 + s1) + (s2 + s3);
        int q = g >> 7, rest = g & 127, nt = rest >> 5, hl = rest & 31;
        g_hbre[b * 512 + nt * 128 + hl * 4 + q] = s;
    } else if (bx < 96) {
        // col n of nf-block: gate = (nf&1)*2 + (n&1); head-local = (n>>1)*2 + (nf>>1)
        int idx = (bx - 64) * 256 + tid;           // [nt][ks][jj][lane]
        int lane = idx & 31, jj = (idx >> 5) & 7, ks = (idx >> 8) & 7, nt = idx >> 11;
        int n = lane >> 2, tt = lane & 3;
        int k0 = ks * 16 + tt * 2;
        uint32_t v[4];
#pragma unroll
        for (int s = 0; s < 2; s++) {
            int NF = jj * 2 + s;
            int wn = NF >> 2, nf = NF & 3;
            int gate  = (nf & 1) * 2 + (n & 1);
            int headl = (n >> 1) * 2 + (nf >> 1);
            int gw = gate * 128 + nt * 32 + wn * 8 + headl;
            const float* wr = W_ih + gw * 128;
            __half2 b0 = __floats2half2_rn(wr[k0], wr[k0 + 1]);
            __half2 b1 = __floats2half2_rn(wr[k0 + 8], wr[k0 + 9]);
            v[s * 2 + 0] = *(uint32_t*)&b0;
            v[s * 2 + 1] = *(uint32_t*)&b1;
        }
        g_wfrag4[idx] = make_uint4(v[0], v[1], v[2], v[3]);
    } else {
        // ---- A frags, fully coalesced both sides ----
        const int mt = bx - 96;                    // 64-row tile, 0..2047
        const float4* ip = (const float4*)(input + (size_t)mt * 64 * 128);
#pragma unroll
        for (int j = 0; j < 8; j++) {
            int i = tid + j * 256;                 // 0..2047 float4s, coalesced
            int row = i >> 5, c4 = i & 31;
            float4 v = ip[i];
            __half2 p0 = __floats2half2_rn(v.x, v.y);
            __half2 p1 = __floats2half2_rn(v.z, v.w);
            *(uint2*)(&As[row * 136 + c4 * 4]) = make_uint2(*(uint32_t*)&p0, *(uint32_t*)&p1);
        }
        __syncthreads();
        uint4* dst = g_afrag + (size_t)mt * 1024;
#pragma unroll
        for (int j = 0; j < 4; j++) {
            int o = tid + j * 256;                 // [ks(8)][rg(4)][lane(32)]
            int lane = o & 31, rg = (o >> 5) & 3, ks = o >> 7;
            int g2 = lane >> 2, t2 = (lane & 3) * 2;
            int r0 = rg * 16 + g2;
            int k0 = ks * 16 + t2;
            uint32_t a0 = *(uint32_t*)&As[r0 * 136 + k0];
            uint32_t a1 = *(uint32_t*)&As[(r0 + 8) * 136 + k0];
            uint32_t a2 = *(uint32_t*)&As[r0 * 136 + k0 + 8];
            uint32_t a3 = *(uint32_t*)&As[(r0 + 8) * 136 + k0 + 8];
            dst[o] = make_uint4(a0, a1, a2, a3);   // coalesced STG.128
        }
    }
}

// ---------------- main kernel ----------------
#define SMEM_BQ  0                 // 32768 : B frags (uint4 x 2048)
#define SMEM_HB  32768             // 16896 : HBs [32][132] f32
#define SMEM_C0  49664             // 4224  : c0   [32][33]
#define SMEM_NZ  53888             // 4224  : noise[32][33]
#define SMEM_TOT 58112

__global__ __launch_bounds__(256, 2)
void lstm_mma(const float* __restrict__ c0, const float* __restrict__ noise,
              float* __restrict__ out) {
    extern __shared__ char sm[];
    uint4* Bs   = (uint4*)(sm + SMEM_BQ);
    float* HBsm = (float*)(sm + SMEM_HB);
    float* C0sm = (float*)(sm + SMEM_C0);
    float* NZsm = (float*)(sm + SMEM_NZ);

    const int tid = threadIdx.x;
    const int wid = tid >> 5, lane = tid & 31;
    const int nt = blockIdx.x & 3, grp = blockIdx.x >> 2;   // grp 0..511
    const int wm = wid & 1, wn = wid >> 1;                  // 2m x 4n (32x32 warp tiles)
    const int g_row = lane >> 2, t = lane & 31 & 3;

    // ---- coalesced staging of B frags + epilogue constants ----
    {
        const uint4* src = g_wfrag4 + nt * 2048;
        for (int i = tid; i < 2048; i += 256) Bs[i] = src[i];
        for (int i = tid; i < 4096; i += 256) {            // hb: contiguous 128/b
            int b = i >> 7, c = i & 127;
            HBsm[b * 132 + c] = g_hbre[b * 512 + nt * 128 + c];
        }
        for (int i = tid; i < 1024; i += 256) {
            int b = i >> 5, hl = i & 31;
            C0sm[b * 33 + hl] = c0[b * 128 + nt * 32 + hl];
            NZsm[b * 33 + hl] = noise[b * 128 + nt * 32 + hl];
        }
    }
    __syncthreads();

    // ---- register-cache ALL epilogue constants from smem (one-time LDS) ----
    float4 hbC[4][2];
    float  c0C[4][2], nzC[4][2];
#pragma unroll
    for (int mi = 0; mi < 4; mi++) {
        const int b = mi * 8 + g_row;
#pragma unroll
        for (int j = 0; j < 2; j++) {
            const int hl = wn * 8 + t * 2 + j;
            float4 hb = *(const float4*)(HBsm + b * 132 + hl * 4);
            hbC[mi][j] = make_float4(hb.x * 0.5f, hb.y * 0.5f, hb.z, hb.w * 0.5f);
            c0C[mi][j] = C0sm[b * 33 + hl];
            nzC[mi][j] = NZsm[b * 33 + hl];
        }
    }

    // A frag base: [mt64][ks(8)][rg(4)][lane]; rg = wm*2 + mf; tile stride 1024
    const uint4* Ag = g_afrag + ((size_t)(grp * 4) * 32 + wm * 2) * 32 + lane;

    uint4 af[2][2];
    af[0][0] = Ag[0];
    af[0][1] = Ag[32];

    for (int tile = 0; tile < 4; tile++) {
        const int r0 = (grp * 4 + tile) * 64;

        float acc[2][4][4];
#pragma unroll
        for (int mf = 0; mf < 2; mf++)
#pragma unroll
            for (int nf = 0; nf < 4; nf++)
#pragma unroll
                for (int r = 0; r < 4; r++) acc[mf][nf][r] = 0.f;

#pragma unroll
        for (int ks = 0; ks < 8; ks++) {
            if (ks < 7) {                          // prefetch next ks (dist 1)
                af[(ks + 1) & 1][0] = Ag[((ks + 1) * 4 + 0) * 32];
                af[(ks + 1) & 1][1] = Ag[((ks + 1) * 4 + 1) * 32];
            } else if (tile < 3) {                 // prefetch next tile ks0 -> buf 0
                af[0][0] = Ag[1024 + 0 * 32];
                af[0][1] = Ag[1024 + 1 * 32];
            }
            const uint4 q0 = Bs[(ks * 8 + wn * 2 + 0) * 32 + lane];
            const uint4 q1 = Bs[(ks * 8 + wn * 2 + 1) * 32 + lane];
#pragma unroll
            for (int mf = 0; mf < 2; mf++) {
                uint4 a = af[ks & 1][mf];
#define MMA_(ACC, BX, BY) \
                asm volatile("mma.sync.aligned.m16n8k16.row.col.f32.f16.f16.f32 " \
                    "{%0,%1,%2,%3}, {%4,%5,%6,%7}, {%8,%9}, {%0,%1,%2,%3};" \
                    : "+f"(ACC[0]), "+f"(ACC[1]), "+f"(ACC[2]), "+f"(ACC[3]) \
                    : "r"(a.x), "r"(a.y), "r"(a.z), "r"(a.w), "r"(BX), "r"(BY))
                MMA_(acc[mf][0], q0.x, q0.y);
                MMA_(acc[mf][1], q0.z, q0.w);
                MMA_(acc[mf][2], q1.x, q1.y);
                MMA_(acc[mf][3], q1.z, q1.w);
#undef MMA_
            }
        }
        Ag += 1024;

        // ---- fused LSTM epilogue: all-register, STG.64 pairs ----
#pragma unroll
        for (int mf = 0; mf < 2; mf++) {
#pragma unroll
            for (int r = 0; r < 2; r++) {
                const int mi = mf * 2 + r;
                const int row = wm * 32 + mf * 16 + g_row + r * 8;
                float hv2[2], cc2[2];
#pragma unroll
                for (int j = 0; j < 2; j++) {
                    float4 hb = hbC[mi][j];
                    float ti = tanh_ap(fmaf(acc[mf][2 * j][2 * r],     0.5f, hb.x));
                    float tf = tanh_ap(fmaf(acc[mf][2 * j][2 * r + 1], 0.5f, hb.y));
                    float tg = tanh_ap(acc[mf][2 * j + 1][2 * r] + hb.z);
                    float to = tanh_ap(fmaf(acc[mf][2 * j + 1][2 * r + 1], 0.5f, hb.w));
                    float si = fmaf(ti, 0.5f, 0.5f);
                    float sf = fmaf(tf, 0.5f, 0.5f);
                    float so = fmaf(to, 0.5f, 0.5f);
                    float cc = sf * c0C[mi][j] + si * tg;
                    float hv = fmaf(so, tanh_ap(cc), nzC[mi][j]);
                    hv2[j] = hv; cc2[j] = cc;
                }
                const int gr = r0 + row;
                *(float2*)(out + (size_t)gr * 128 + nt * 32 + wn * 8 + t * 2) =
                    make_float2(hv2[0], hv2[1]);
                if (gr >= TB_ - 32) {              // last timestep rows
                    size_t base = (size_t)TB_ * 128 + (size_t)(mi * 8 + g_row) * 128
                                + nt * 32 + wn * 8 + t * 2;
                    *(float2*)(out + base)        = make_float2(hv2[0], hv2[1]);
                    *(float2*)(out + base + 4096) = make_float2(cc2[0], cc2[1]);
                }
            }
        }
    }
}

// ---------------- launch ----------------
extern "C" void kernel_launch(void* const* d_in, const int* in_sizes, int n_in,
                              void* d_out, int out_size) {
    const float* input = (const float*)d_in[0];
    const float* h0    = (const float*)d_in[1];
    const float* c0    = (const float*)d_in[2];
    const float* noise = (const float*)d_in[3];
    const float* W_ih  = (const float*)d_in[4];
    const float* W_hh  = (const float*)d_in[5];
    const float* b_ih  = (const float*)d_in[6];
    const float* b_hh  = (const float*)d_in[7];
    float* out = (float*)d_out;

    prep_all<<<96 + 2048, 256>>>(input, h0, W_hh, b_ih, b_hh, W_ih);

    cudaFuncSetAttribute(lstm_mma, cudaFuncAttributeMaxDynamicSharedMemorySize, SMEM_TOT);
    lstm_mma<<<2048, 256, SMEM_TOT>>>(c0, noise, out);
}

// round 16
// speedup vs baseline: 1.1920x; 1.1920x over previous
#include <cuda_runtime.h>
#include <cuda_fp16.h>
#include <cstdint>

#define TB_ 131072
#define B_  32

// ---------------- device scratch (no allocation allowed) ----------------
__device__ float g_hbre[B_ * 512];             // [b][nt*128 + hl*4 + q]
__device__ uint4 g_wfrag4[4 * 8 * 8 * 32];     // [nt][ks][jj][lane] -> {bA0,bA1,bB0,bB1}
// A frags for 64-row tiles: [mt64(2048)][ks(8)][rg(4)][lane(32)] -> uint4
__device__ uint4 g_afrag[2048 * 8 * 4 * 32];   // 33.5 MB

// ---------------- helpers ----------------
__device__ __forceinline__ float tanh_ap(float x) {
    float y; asm("tanh.approx.f32 %0, %1;" : "=f"(y) : "f"(x)); return y;
}

// ---------------- fused prep kernel (R14: coalesced A-convert) ----------------
// blocks [0,64):     Hb = h0 @ W_hh^T + b_ih + b_hh (gate-interleaved layout)
// blocks [64,96):    W_ih -> fp16 B-frag uint4 pairs, in-lane gate/head mapping
// blocks [96,2144):  input fp32 -> fp16 A frags via coalesced smem transpose
__global__ void prep_all(const float* __restrict__ input, const float* __restrict__ h0,
                         const float* __restrict__ W_hh, const float* __restrict__ b_ih,
                         const float* __restrict__ b_hh, const float* __restrict__ W_ih) {
    __shared__ __align__(16) unsigned short As[64 * 136];   // padded fp16 tile (17.4 KB)
    const int bx = blockIdx.x, tid = threadIdx.x;
    if (bx < 64) {
        int idx = bx * 256 + tid;
        int b = idx & 31, g = idx >> 5;
        const float4* wv = (const float4*)(W_hh + g * 128);
        const float4* hv = (const float4*)(h0 + b * 128);
        float s0 = b_ih[g] + b_hh[g], s1 = 0.f, s2 = 0.f, s3 = 0.f;
#pragma unroll
        for (int k = 0; k < 32; k++) {
            float4 w = wv[k], h = hv[k];
            s0 += w.x * h.x; s1 += w.y * h.y; s2 += w.z * h.z; s3 += w.w * h.w;
        }
        float s = (s0 + s1) + (s2 + s3);
        int q = g >> 7, rest = g & 127, nt = rest >> 5, hl = rest & 31;
        g_hbre[b * 512 + nt * 128 + hl * 4 + q] = s;
    } else if (bx < 96) {
        // col n of nf-block: gate = (nf&1)*2 + (n&1); head-local = (n>>1)*2 + (nf>>1)
        int idx = (bx - 64) * 256 + tid;           // [nt][ks][jj][lane]
        int lane = idx & 31, jj = (idx >> 5) & 7, ks = (idx >> 8) & 7, nt = idx >> 11;
        int n = lane >> 2, tt = lane & 3;
        int k0 = ks * 16 + tt * 2;
        uint32_t v[4];
#pragma unroll
        for (int s = 0; s < 2; s++) {
            int NF = jj * 2 + s;
            int wn = NF >> 2, nf = NF & 3;
            int gate  = (nf & 1) * 2 + (n & 1);
            int headl = (n >> 1) * 2 + (nf >> 1);
            int gw = gate * 128 + nt * 32 + wn * 8 + headl;
            const float* wr = W_ih + gw * 128;
            __half2 b0 = __floats2half2_rn(wr[k0], wr[k0 + 1]);
            __half2 b1 = __floats2half2_rn(wr[k0 + 8], wr[k0 + 9]);
            v[s * 2 + 0] = *(uint32_t*)&b0;
            v[s * 2 + 1] = *(uint32_t*)&b1;
        }
        g_wfrag4[idx] = make_uint4(v[0], v[1], v[2], v[3]);
    } else {
        // ---- A frags, fully coalesced both sides ----
        const int mt = bx - 96;                    // 64-row tile, 0..2047
        const float4* ip = (const float4*)(input + (size_t)mt * 64 * 128);
#pragma unroll
        for (int j = 0; j < 8; j++) {
            int i = tid + j * 256;                 // 0..2047 float4s, coalesced
            int row = i >> 5, c4 = i & 31;
            float4 v = ip[i];
            __half2 p0 = __floats2half2_rn(v.x, v.y);
            __half2 p1 = __floats2half2_rn(v.z, v.w);
            *(uint2*)(&As[row * 136 + c4 * 4]) = make_uint2(*(uint32_t*)&p0, *(uint32_t*)&p1);
        }
        __syncthreads();
        uint4* dst = g_afrag + (size_t)mt * 1024;
#pragma unroll
        for (int j = 0; j < 4; j++) {
            int o = tid + j * 256;                 // [ks(8)][rg(4)][lane(32)]
            int lane = o & 31, rg = (o >> 5) & 3, ks = o >> 7;
            int g2 = lane >> 2, t2 = (lane & 3) * 2;
            int r0 = rg * 16 + g2;
            int k0 = ks * 16 + t2;
            uint32_t a0 = *(uint32_t*)&As[r0 * 136 + k0];
            uint32_t a1 = *(uint32_t*)&As[(r0 + 8) * 136 + k0];
            uint32_t a2 = *(uint32_t*)&As[r0 * 136 + k0 + 8];
            uint32_t a3 = *(uint32_t*)&As[(r0 + 8) * 136 + k0 + 8];
            dst[o] = make_uint4(a0, a1, a2, a3);   // coalesced STG.128
        }
    }
}

// ---------------- main kernel (VERBATIM from round 13, 85.9us measured) ----------------
__global__ __launch_bounds__(256, 2)
void lstm_mma(const float* __restrict__ c0, const float* __restrict__ noise,
              float* __restrict__ out) {
    __shared__ uint4 Bs[2048];                    // 32 KB static

    const int tid = threadIdx.x;
    const int wid = tid >> 5, lane = tid & 31;
    const int nt = blockIdx.x & 3, grp = blockIdx.x >> 2;   // grp 0..511
    const int wm = wid & 1, wn = wid >> 1;                  // 2m x 4n (32x32 warp tiles)
    const int g_row = lane >> 2, t = lane & 3;

    // ---- stage B fragments (only smem use) ----
    {
        const uint4* src = g_wfrag4 + nt * 2048;
        for (int i = tid; i < 2048; i += 256) Bs[i] = src[i];
    }

    // ---- register-cache epilogue constants (tile-invariant per lane) ----
    float4 hbC[4][2];
    float  c0C[4][2], nzC[4][2];
#pragma unroll
    for (int mi = 0; mi < 4; mi++) {
        const int b = mi * 8 + g_row;
#pragma unroll
        for (int j = 0; j < 2; j++) {
            const int hl = wn * 8 + t * 2 + j;
            float4 hb = *(const float4*)(g_hbre + b * 512 + nt * 128 + hl * 4);
            hbC[mi][j] = make_float4(hb.x * 0.5f, hb.y * 0.5f, hb.z, hb.w * 0.5f);
            c0C[mi][j] = c0[b * 128 + nt * 32 + hl];
            nzC[mi][j] = noise[b * 128 + nt * 32 + hl];
        }
    }
    __syncthreads();

    // A frag base: [mt64][ks(8)][rg(4)][lane]; rg = wm*2 + mf; tile stride 1024
    const uint4* Ag = g_afrag + ((size_t)(grp * 4) * 32 + wm * 2) * 32 + lane;

    uint4 af[2][2];
    af[0][0] = Ag[0];
    af[0][1] = Ag[32];

    for (int tile = 0; tile < 4; tile++) {
        const int r0 = (grp * 4 + tile) * 64;

        float acc[2][4][4];
#pragma unroll
        for (int mf = 0; mf < 2; mf++)
#pragma unroll
            for (int nf = 0; nf < 4; nf++)
#pragma unroll
                for (int r = 0; r < 4; r++) acc[mf][nf][r] = 0.f;

#pragma unroll
        for (int ks = 0; ks < 8; ks++) {
            if (ks < 7) {                          // prefetch next ks (dist 1)
                af[(ks + 1) & 1][0] = Ag[((ks + 1) * 4 + 0) * 32];
                af[(ks + 1) & 1][1] = Ag[((ks + 1) * 4 + 1) * 32];
            } else if (tile < 3) {                 // prefetch next tile ks0 -> buf 0
                af[0][0] = Ag[1024 + 0 * 32];
                af[0][1] = Ag[1024 + 1 * 32];
            }
            const uint4 q0 = Bs[(ks * 8 + wn * 2 + 0) * 32 + lane];
            const uint4 q1 = Bs[(ks * 8 + wn * 2 + 1) * 32 + lane];
#pragma unroll
            for (int mf = 0; mf < 2; mf++) {
                uint4 a = af[ks & 1][mf];
#define MMA_(ACC, BX, BY) \
                asm volatile("mma.sync.aligned.m16n8k16.row.col.f32.f16.f16.f32 " \
                    "{%0,%1,%2,%3}, {%4,%5,%6,%7}, {%8,%9}, {%0,%1,%2,%3};" \
                    : "+f"(ACC[0]), "+f"(ACC[1]), "+f"(ACC[2]), "+f"(ACC[3]) \
                    : "r"(a.x), "r"(a.y), "r"(a.z), "r"(a.w), "r"(BX), "r"(BY))
                MMA_(acc[mf][0], q0.x, q0.y);
                MMA_(acc[mf][1], q0.z, q0.w);
                MMA_(acc[mf][2], q1.x, q1.y);
                MMA_(acc[mf][3], q1.z, q1.w);
#undef MMA_
            }
        }
        Ag += 1024;

        // ---- fused LSTM epilogue: all-register, STG.64 pairs ----
#pragma unroll
        for (int mf = 0; mf < 2; mf++) {
#pragma unroll
            for (int r = 0; r < 2; r++) {
                const int mi = mf * 2 + r;
                const int row = wm * 32 + mf * 16 + g_row + r * 8;
                float hv2[2], cc2[2];
#pragma unroll
                for (int j = 0; j < 2; j++) {
                    float4 hb = hbC[mi][j];
                    float ti = tanh_ap(fmaf(acc[mf][2 * j][2 * r],     0.5f, hb.x));
                    float tf = tanh_ap(fmaf(acc[mf][2 * j][2 * r + 1], 0.5f, hb.y));
                    float tg = tanh_ap(acc[mf][2 * j + 1][2 * r] + hb.z);
                    float to = tanh_ap(fmaf(acc[mf][2 * j + 1][2 * r + 1], 0.5f, hb.w));
                    float si = fmaf(ti, 0.5f, 0.5f);
                    float sf = fmaf(tf, 0.5f, 0.5f);
                    float so = fmaf(to, 0.5f, 0.5f);
                    float cc = sf * c0C[mi][j] + si * tg;
                    float hv = fmaf(so, tanh_ap(cc), nzC[mi][j]);
                    hv2[j] = hv; cc2[j] = cc;
                }
                const int gr = r0 + row;
                *(float2*)(out + (size_t)gr * 128 + nt * 32 + wn * 8 + t * 2) =
                    make_float2(hv2[0], hv2[1]);
                if (gr >= TB_ - 32) {              // last timestep rows
                    size_t base = (size_t)TB_ * 128 + (size_t)(mi * 8 + g_row) * 128
                                + nt * 32 + wn * 8 + t * 2;
                    *(float2*)(out + base)        = make_float2(hv2[0], hv2[1]);
                    *(float2*)(out + base + 4096) = make_float2(cc2[0], cc2[1]);
                }
            }
        }
    }
}

// ---------------- launch ----------------
extern "C" void kernel_launch(void* const* d_in, const int* in_sizes, int n_in,
                              void* d_out, int out_size) {
    const float* input = (const float*)d_in[0];
    const float* h0    = (const float*)d_in[1];
    const float* c0    = (const float*)d_in[2];
    const float* noise = (const float*)d_in[3];
    const float* W_ih  = (const float*)d_in[4];
    const float* W_hh  = (const float*)d_in[5];
    const float* b_ih  = (const float*)d_in[6];
    const float* b_hh  = (const float*)d_in[7];
    float* out = (float*)d_out;

    prep_all<<<96 + 2048, 256>>>(input, h0, W_hh, b_ih, b_hh, W_ih);
    lstm_mma<<<2048, 256>>>(c0, noise, out);
}

// round 17
// speedup vs baseline: 1.2638x; 1.0602x over previous
#include <cuda_runtime.h>
#include <cuda_fp16.h>
#include <cstdint>

#define TB_ 131072
#define B_  32

// ---------------- device scratch (no allocation allowed) ----------------
__device__ float g_hbre[B_ * 512];             // [b][nt*128 + hl*4 + q]
__device__ uint4 g_wfrag4[4 * 8 * 8 * 32];     // [nt][ks][jj][lane] -> {bA0,bA1,bB0,bB1}
// A frags for 64-row tiles: [mt64(2048)][ks(8)][rg(4)][lane(32)] -> uint4 (16KB/tile)
__device__ uint4 g_afrag[2048 * 8 * 4 * 32];   // 33.5 MB

// ---------------- helpers ----------------
__device__ __forceinline__ float tanh_ap(float x) {
    float y; asm("tanh.approx.f32 %0, %1;" : "=f"(y) : "f"(x)); return y;
}
__device__ __forceinline__ uint32_t smem_u32(const void* p) {
    uint32_t a;
    asm("{ .reg .u64 t; cvta.to.shared.u64 t, %1; cvt.u32.u64 %0, t; }" : "=r"(a) : "l"(p));
    return a;
}

// ---------------- fused prep kernel (R14/R16: coalesced A-convert) ----------------
__global__ void prep_all(const float* __restrict__ input, const float* __restrict__ h0,
                         const float* __restrict__ W_hh, const float* __restrict__ b_ih,
                         const float* __restrict__ b_hh, const float* __restrict__ W_ih) {
    __shared__ __align__(16) unsigned short As[64 * 136];   // padded fp16 tile (17.4 KB)
    const int bx = blockIdx.x, tid = threadIdx.x;
    if (bx < 64) {
        int idx = bx * 256 + tid;
        int b = idx & 31, g = idx >> 5;
        const float4* wv = (const float4*)(W_hh + g * 128);
        const float4* hv = (const float4*)(h0 + b * 128);
        float s0 = b_ih[g] + b_hh[g], s1 = 0.f, s2 = 0.f, s3 = 0.f;
#pragma unroll
        for (int k = 0; k < 32; k++) {
            float4 w = wv[k], h = hv[k];
            s0 += w.x * h.x; s1 += w.y * h.y; s2 += w.z * h.z; s3 += w.w * h.w;
        }
        float s = (s0 + s1) + (s2 + s3);
        int q = g >> 7, rest = g & 127, nt = rest >> 5, hl = rest & 31;
        g_hbre[b * 512 + nt * 128 + hl * 4 + q] = s;
    } else if (bx < 96) {
        // col n of nf-block: gate = (nf&1)*2 + (n&1); head-local = (n>>1)*2 + (nf>>1)
        int idx = (bx - 64) * 256 + tid;           // [nt][ks][jj][lane]
        int lane = idx & 31, jj = (idx >> 5) & 7, ks = (idx >> 8) & 7, nt = idx >> 11;
        int n = lane >> 2, tt = lane & 3;
        int k0 = ks * 16 + tt * 2;
        uint32_t v[4];
#pragma unroll
        for (int s = 0; s < 2; s++) {
            int NF = jj * 2 + s;
            int wn = NF >> 2, nf = NF & 3;
            int gate  = (nf & 1) * 2 + (n & 1);
            int headl = (n >> 1) * 2 + (nf >> 1);
            int gw = gate * 128 + nt * 32 + wn * 8 + headl;
            const float* wr = W_ih + gw * 128;
            __half2 b0 = __floats2half2_rn(wr[k0], wr[k0 + 1]);
            __half2 b1 = __floats2half2_rn(wr[k0 + 8], wr[k0 + 9]);
            v[s * 2 + 0] = *(uint32_t*)&b0;
            v[s * 2 + 1] = *(uint32_t*)&b1;
        }
        g_wfrag4[idx] = make_uint4(v[0], v[1], v[2], v[3]);
    } else {
        // ---- A frags, fully coalesced both sides ----
        const int mt = bx - 96;                    // 64-row tile, 0..2047
        const float4* ip = (const float4*)(input + (size_t)mt * 64 * 128);
#pragma unroll
        for (int j = 0; j < 8; j++) {
            int i = tid + j * 256;                 // 0..2047 float4s, coalesced
            int row = i >> 5, c4 = i & 31;
            float4 v = ip[i];
            __half2 p0 = __floats2half2_rn(v.x, v.y);
            __half2 p1 = __floats2half2_rn(v.z, v.w);
            *(uint2*)(&As[row * 136 + c4 * 4]) = make_uint2(*(uint32_t*)&p0, *(uint32_t*)&p1);
        }
        __syncthreads();
        uint4* dst = g_afrag + (size_t)mt * 1024;
#pragma unroll
        for (int j = 0; j < 4; j++) {
            int o = tid + j * 256;                 // [ks(8)][rg(4)][lane(32)]
            int lane = o & 31, rg = (o >> 5) & 3, ks = o >> 7;
            int g2 = lane >> 2, t2 = (lane & 3) * 2;
            int r0 = rg * 16 + g2;
            int k0 = ks * 16 + t2;
            uint32_t a0 = *(uint32_t*)&As[r0 * 136 + k0];
            uint32_t a1 = *(uint32_t*)&As[(r0 + 8) * 136 + k0];
            uint32_t a2 = *(uint32_t*)&As[r0 * 136 + k0 + 8];
            uint32_t a3 = *(uint32_t*)&As[(r0 + 8) * 136 + k0 + 8];
            dst[o] = make_uint4(a0, a1, a2, a3);   // coalesced STG.128
        }
    }
}

// ---------------- main kernel: cp.async tile-deep A pipeline ----------------
#define SMEM_TOT 65536   // 32KB B frags + 2 x 16KB A tile ring

__global__ __launch_bounds__(256, 2)
void lstm_mma(const float* __restrict__ c0, const float* __restrict__ noise,
              float* __restrict__ out) {
    extern __shared__ char sm[];
    uint4* Bs  = (uint4*)sm;                       // 32 KB
    uint4* Asm = (uint4*)(sm + 32768);             // 2 x 1024 uint4

    const int tid = threadIdx.x;
    const int wid = tid >> 5, lane = tid & 31;
    const int nt = blockIdx.x & 3, grp = blockIdx.x >> 2;   // grp 0..511
    const int wm = wid & 1, wn = wid >> 1;                  // 2m x 4n (32x32 warp tiles)
    const int g_row = lane >> 2, t = lane & 3;
    const uint32_t smb = smem_u32(sm);

    // ---- prologue: async-copy A tiles 0 and 1 into the ring ----
    {
        const char* s0 = (const char*)(g_afrag + (size_t)(grp * 4 + 0) * 1024) + tid * 16;
        const char* s1 = (const char*)(g_afrag + (size_t)(grp * 4 + 1) * 1024) + tid * 16;
        uint32_t d0 = smb + 32768 + tid * 16;
        uint32_t d1 = d0 + 16384;
#pragma unroll
        for (int j = 0; j < 4; j++)
            asm volatile("cp.async.cg.shared.global [%0],[%1],16;" :: "r"(d0 + j * 4096), "l"(s0 + j * 4096));
        asm volatile("cp.async.commit_group;");
#pragma unroll
        for (int j = 0; j < 4; j++)
            asm volatile("cp.async.cg.shared.global [%0],[%1],16;" :: "r"(d1 + j * 4096), "l"(s1 + j * 4096));
        asm volatile("cp.async.commit_group;");
    }

    // ---- stage B fragments ----
    {
        const uint4* src = g_wfrag4 + nt * 2048;
        for (int i = tid; i < 2048; i += 256) Bs[i] = src[i];
    }

    // ---- register-cache epilogue constants (tile-invariant per lane) ----
    float4 hbC[4][2];
    float  c0C[4][2], nzC[4][2];
#pragma unroll
    for (int mi = 0; mi < 4; mi++) {
        const int b = mi * 8 + g_row;
#pragma unroll
        for (int j = 0; j < 2; j++) {
            const int hl = wn * 8 + t * 2 + j;
            float4 hb = *(const float4*)(g_hbre + b * 512 + nt * 128 + hl * 4);
            hbC[mi][j] = make_float4(hb.x * 0.5f, hb.y * 0.5f, hb.z, hb.w * 0.5f);
            c0C[mi][j] = c0[b * 128 + nt * 32 + hl];
            nzC[mi][j] = noise[b * 128 + nt * 32 + hl];
        }
    }
    __syncthreads();

    for (int tile = 0; tile < 4; tile++) {
        const int r0 = (grp * 4 + tile) * 64;
        // wait: all groups except the most recent one are complete -> this tile's
        asm volatile("cp.async.wait_group 1;" ::: "memory");
        __syncthreads();

        const uint4* At = Asm + (tile & 1) * 1024;   // this tile's A frags in smem

        float acc[2][4][4];
#pragma unroll
        for (int mf = 0; mf < 2; mf++)
#pragma unroll
            for (int nf = 0; nf < 4; nf++)
#pragma unroll
                for (int r = 0; r < 4; r++) acc[mf][nf][r] = 0.f;

        uint4 af[2][2];
        af[0][0] = At[(0 * 4 + wm * 2 + 0) * 32 + lane];
        af[0][1] = At[(0 * 4 + wm * 2 + 1) * 32 + lane];

#pragma unroll
        for (int ks = 0; ks < 8; ks++) {
            if (ks < 7) {                          // dist-1 prefetch from smem (29cyc)
                af[(ks + 1) & 1][0] = At[((ks + 1) * 4 + wm * 2 + 0) * 32 + lane];
                af[(ks + 1) & 1][1] = At[((ks + 1) * 4 + wm * 2 + 1) * 32 + lane];
            }
            const uint4 q0 = Bs[(ks * 8 + wn * 2 + 0) * 32 + lane];
            const uint4 q1 = Bs[(ks * 8 + wn * 2 + 1) * 32 + lane];
#pragma unroll
            for (int mf = 0; mf < 2; mf++) {
                uint4 a = af[ks & 1][mf];
#define MMA_(ACC, BX, BY) \
                asm volatile("mma.sync.aligned.m16n8k16.row.col.f32.f16.f16.f32 " \
                    "{%0,%1,%2,%3}, {%4,%5,%6,%7}, {%8,%9}, {%0,%1,%2,%3};" \
                    : "+f"(ACC[0]), "+f"(ACC[1]), "+f"(ACC[2]), "+f"(ACC[3]) \
                    : "r"(a.x), "r"(a.y), "r"(a.z), "r"(a.w), "r"(BX), "r"(BY))
                MMA_(acc[mf][0], q0.x, q0.y);
                MMA_(acc[mf][1], q0.z, q0.w);
                MMA_(acc[mf][2], q1.x, q1.y);
                MMA_(acc[mf][3], q1.z, q1.w);
#undef MMA_
            }
        }
        __syncthreads();                           // all reads of this buffer done

        // ---- async-copy tile+2 into the freed buffer (flies under epilogue) ----
        if (tile + 2 < 4) {
            const char* s2 = (const char*)(g_afrag + (size_t)(grp * 4 + tile + 2) * 1024) + tid * 16;
            uint32_t d2 = smb + 32768 + (tile & 1) * 16384 + tid * 16;
#pragma unroll
            for (int j = 0; j < 4; j++)
                asm volatile("cp.async.cg.shared.global [%0],[%1],16;" :: "r"(d2 + j * 4096), "l"(s2 + j * 4096));
        }
        asm volatile("cp.async.commit_group;");    // uniform group accounting

        // ---- fused LSTM epilogue: all-register, STG.64 pairs (verbatim R16) ----
#pragma unroll
        for (int mf = 0; mf < 2; mf++) {
#pragma unroll
            for (int r = 0; r < 2; r++) {
                const int mi = mf * 2 + r;
                const int row = wm * 32 + mf * 16 + g_row + r * 8;
                float hv2[2], cc2[2];
#pragma unroll
                for (int j = 0; j < 2; j++) {
                    float4 hb = hbC[mi][j];
                    float ti = tanh_ap(fmaf(acc[mf][2 * j][2 * r],     0.5f, hb.x));
                    float tf = tanh_ap(fmaf(acc[mf][2 * j][2 * r + 1], 0.5f, hb.y));
                    float tg = tanh_ap(acc[mf][2 * j + 1][2 * r] + hb.z);
                    float to = tanh_ap(fmaf(acc[mf][2 * j + 1][2 * r + 1], 0.5f, hb.w));
                    float si = fmaf(ti, 0.5f, 0.5f);
                    float sf = fmaf(tf, 0.5f, 0.5f);
                    float so = fmaf(to, 0.5f, 0.5f);
                    float cc = sf * c0C[mi][j] + si * tg;
                    float hv = fmaf(so, tanh_ap(cc), nzC[mi][j]);
                    hv2[j] = hv; cc2[j] = cc;
                }
                const int gr = r0 + row;
                *(float2*)(out + (size_t)gr * 128 + nt * 32 + wn * 8 + t * 2) =
                    make_float2(hv2[0], hv2[1]);
                if (gr >= TB_ - 32) {              // last timestep rows
                    size_t base = (size_t)TB_ * 128 + (size_t)(mi * 8 + g_row) * 128
                                + nt * 32 + wn * 8 + t * 2;
                    *(float2*)(out + base)        = make_float2(hv2[0], hv2[1]);
                    *(float2*)(out + base + 4096) = make_float2(cc2[0], cc2[1]);
                }
            }
        }
    }
}

// ---------------- launch ----------------
extern "C" void kernel_launch(void* const* d_in, const int* in_sizes, int n_in,
                              void* d_out, int out_size) {
    const float* input = (const float*)d_in[0];
    const float* h0    = (const float*)d_in[1];
    const float* c0    = (const float*)d_in[2];
    const float* noise = (const float*)d_in[3];
    const float* W_ih  = (const float*)d_in[4];
    const float* W_hh  = (const float*)d_in[5];
    const float* b_ih  = (const float*)d_in[6];
    const float* b_hh  = (const float*)d_in[7];
    float* out = (float*)d_out;

    prep_all<<<96 + 2048, 256>>>(input, h0, W_hh, b_ih, b_hh, W_ih);

    cudaFuncSetAttribute(lstm_mma, cudaFuncAttributeMaxDynamicSharedMemorySize, SMEM_TOT);
    lstm_mma<<<2048, 256, SMEM_TOT>>>(c0, noise, out);
}